// round 3
// baseline (speedup 1.0000x reference)
#include <cuda_runtime.h>
#include <math_constants.h>

#define BATCH 2
#define N1 4096
#define N2 32768
#define C1 128
#define C2 64
#define F1 128
#define F2 128
#define IN0S 131   // 3 + C1
#define IN1S 67    // 3 + C2
#define KEPS 1e-7f

// Scratch (static device globals: allocation-free)
__device__ float g_PW[BATCH * N1 * F1];   // points1 @ W1[0:128,:]  (4 MB)
__device__ int   g_idx[BATCH * N2 * 3];
__device__ float g_w[BATCH * N2 * 3];

// ---------------------------------------------------------------------------
// K0: PW[b,j,f] = sum_c points1[b,j,c] * W1[c,f]   (rows 0..127 of W1)
// 128 threads, 8 rows per block. 1024 blocks.
// ---------------------------------------------------------------------------
__global__ void pw_kernel(const float* __restrict__ in0, const float* __restrict__ W1) {
    __shared__ float srow[8][128];
    int tid = threadIdx.x;
    long rowbase = (long)blockIdx.x * 8;   // global row in [0, BATCH*N1)
    #pragma unroll
    for (int r = 0; r < 8; r++)
        srow[r][tid] = in0[(rowbase + r) * IN0S + 3 + tid];
    __syncthreads();
    float acc[8];
    #pragma unroll
    for (int r = 0; r < 8; r++) acc[r] = 0.f;
    #pragma unroll 4
    for (int k = 0; k < 128; k++) {
        float w = __ldg(&W1[k * F1 + tid]);
        #pragma unroll
        for (int r = 0; r < 8; r++) acc[r] = fmaf(srow[r][k], w, acc[r]);
    }
    #pragma unroll
    for (int r = 0; r < 8; r++)
        g_PW[(rowbase + r) * F1 + tid] = acc[r];
}

// ---------------------------------------------------------------------------
// K1: brute-force 3-NN per query + inverse-distance weights.
// d(q,p) = |p|^2 - 2 p.q + |q|^2 ; |q|^2 folded in at the end (shifted space)
// -> 3 FFMA + 1 compare per candidate. Writes idx/w scratch and xyz2 output.
// ---------------------------------------------------------------------------
__global__ void knn_kernel(const float* __restrict__ in0, const float* __restrict__ in1,
                           float* __restrict__ out_xyz, int write_xyz) {
    __shared__ float4 tile[1024];
    int b = blockIdx.y;
    int n = blockIdx.x * 256 + threadIdx.x;
    int g = b * N2 + n;
    const float* q = in1 + (size_t)g * IN1S;
    float qx = q[0], qy = q[1], qz = q[2];
    float nqx = -2.f * qx, nqy = -2.f * qy, nqz = -2.f * qz;
    float qq = fmaf(qx, qx, fmaf(qy, qy, qz * qz));
    float e0 = CUDART_INF_F, e1 = CUDART_INF_F, e2 = CUDART_INF_F;
    int i0 = 0, i1 = 0, i2 = 0;

    for (int t = 0; t < N1 / 1024; t++) {
        for (int s = threadIdx.x; s < 1024; s += 256) {
            const float* p = in0 + (size_t)(b * N1 + t * 1024 + s) * IN0S;
            float px = p[0], py = p[1], pz = p[2];
            tile[s] = make_float4(px, py, pz, fmaf(px, px, fmaf(py, py, pz * pz)));
        }
        __syncthreads();
        #pragma unroll 4
        for (int s = 0; s < 1024; s++) {
            float4 p = tile[s];
            float d = fmaf(p.x, nqx, p.w);
            d = fmaf(p.y, nqy, d);
            d = fmaf(p.z, nqz, d);
            if (d < e2) {
                int j = t * 1024 + s;
                if (d < e1) {
                    e2 = e1; i2 = i1;
                    if (d < e0) { e1 = e0; i1 = i0; e0 = d; i0 = j; }
                    else        { e1 = d;  i1 = j; }
                } else { e2 = d; i2 = j; }
            }
        }
        __syncthreads();
    }

    float d0 = fmaxf(e0 + qq, KEPS);
    float d1 = fmaxf(e1 + qq, KEPS);
    float d2 = fmaxf(e2 + qq, KEPS);
    float w0 = 1.f / d0, w1 = 1.f / d1, w2 = 1.f / d2;
    float inv = 1.f / (w0 + w1 + w2);
    g_idx[g * 3 + 0] = i0; g_idx[g * 3 + 1] = i1; g_idx[g * 3 + 2] = i2;
    g_w[g * 3 + 0] = w0 * inv; g_w[g * 3 + 1] = w1 * inv; g_w[g * 3 + 2] = w2 * inv;
    if (write_xyz) {
        out_xyz[(size_t)g * 3 + 0] = qx;
        out_xyz[(size_t)g * 3 + 1] = qy;
        out_xyz[(size_t)g * 3 + 2] = qz;
    }
}

// ---------------------------------------------------------------------------
// K2: fused MLP. 64-query tile per block, 256 threads, 8x4 register sub-tiles.
// H = relu( gather(PW, idx, w) + x2 @ W1[128:192,:] + b1 )
// out = relu( H @ W2 + b2 )
// smem: W2(64K) + W1b(32K) + A(16K) + H(32K) + biases -> 148,480 B dynamic.
// ---------------------------------------------------------------------------
__global__ void mlp_kernel(const float* __restrict__ in1, const float* __restrict__ W1,
                           const float* __restrict__ b1, const float* __restrict__ W2,
                           const float* __restrict__ b2, float* __restrict__ out) {
    extern __shared__ float sm[];
    float* sW2  = sm;             // 16384 floats
    float* sW1b = sW2 + 16384;    //  8192
    float* sA   = sW1b + 8192;    //  4096 (64 queries x 64 feats)
    float* sH   = sA + 4096;      //  8192 (64 x 128)
    float* sB1  = sH + 8192;      //   128
    float* sB2  = sB1 + 128;      //   128

    int tid = threadIdx.x;
    int g0 = blockIdx.x * 64;          // first query of tile
    int bb = g0 / N2;                  // batch (tiles never straddle batches)

    for (int i = tid; i < 16384; i += 256) sW2[i] = W2[i];
    for (int i = tid; i < 8192;  i += 256) sW1b[i] = W1[C1 * F1 + i];
    if (tid < 128) { sB1[tid] = b1[tid]; sB2[tid] = b2[tid]; }
    for (int i = tid; i < 64 * 64; i += 256) {
        int m = i >> 6, c = i & 63;
        sA[i] = in1[(size_t)(g0 + m) * IN1S + 3 + c];
    }
    __syncthreads();

    // Gather interpolation in projected space into sH (4 threads per query row)
    {
        int m  = tid >> 2;
        int fo = (tid & 3) * 32;
        int g  = g0 + m;
        int j0 = g_idx[g * 3 + 0], j1 = g_idx[g * 3 + 1], j2 = g_idx[g * 3 + 2];
        float w0 = g_w[g * 3 + 0], w1 = g_w[g * 3 + 1], w2 = g_w[g * 3 + 2];
        const float* P  = g_PW + (size_t)bb * N1 * F1;
        const float* p0 = P + (size_t)j0 * F1;
        const float* p1 = P + (size_t)j1 * F1;
        const float* p2 = P + (size_t)j2 * F1;
        #pragma unroll
        for (int u = 0; u < 32; u += 4) {
            int f = fo + u;
            float4 a  = *(const float4*)(p0 + f);
            float4 c4 = *(const float4*)(p1 + f);
            float4 e4 = *(const float4*)(p2 + f);
            float4 bv = *(const float4*)(sB1 + f);
            float4 r;
            r.x = bv.x + w0 * a.x + w1 * c4.x + w2 * e4.x;
            r.y = bv.y + w0 * a.y + w1 * c4.y + w2 * e4.y;
            r.z = bv.z + w0 * a.z + w1 * c4.z + w2 * e4.z;
            r.w = bv.w + w0 * a.w + w1 * c4.w + w2 * e4.w;
            *(float4*)(sH + m * 128 + f) = r;
        }
    }
    __syncthreads();

    int tc = tid & 31, tr = tid >> 5;
    int nn = tc * 4;

    // init accumulators from gathered interp contribution
    float acc[8][4];
    #pragma unroll
    for (int i = 0; i < 8; i++) {
        float4 v = *(const float4*)(sH + (tr * 8 + i) * 128 + nn);
        acc[i][0] = v.x; acc[i][1] = v.y; acc[i][2] = v.z; acc[i][3] = v.w;
    }
    __syncthreads();   // all reads of sH-init done before it is overwritten

    // GEMM1: A(64x64) @ W1b(64x128)
    #pragma unroll 4
    for (int k = 0; k < 64; k++) {
        float4 wv = *(const float4*)(sW1b + k * 128 + nn);
        #pragma unroll
        for (int i = 0; i < 8; i++) {
            float a = sA[(tr * 8 + i) * 64 + k];
            acc[i][0] = fmaf(a, wv.x, acc[i][0]);
            acc[i][1] = fmaf(a, wv.y, acc[i][1]);
            acc[i][2] = fmaf(a, wv.z, acc[i][2]);
            acc[i][3] = fmaf(a, wv.w, acc[i][3]);
        }
    }

    // relu -> sH
    #pragma unroll
    for (int i = 0; i < 8; i++) {
        float4 v;
        v.x = fmaxf(acc[i][0], 0.f);
        v.y = fmaxf(acc[i][1], 0.f);
        v.z = fmaxf(acc[i][2], 0.f);
        v.w = fmaxf(acc[i][3], 0.f);
        *(float4*)(sH + (tr * 8 + i) * 128 + nn) = v;
    }
    __syncthreads();

    // GEMM2: H(64x128) @ W2(128x128)
    float4 b2v = *(const float4*)(sB2 + nn);
    float acc2[8][4];
    #pragma unroll
    for (int i = 0; i < 8; i++) {
        acc2[i][0] = b2v.x; acc2[i][1] = b2v.y; acc2[i][2] = b2v.z; acc2[i][3] = b2v.w;
    }
    #pragma unroll 2
    for (int k = 0; k < 128; k++) {
        float4 wv = *(const float4*)(sW2 + k * 128 + nn);
        #pragma unroll
        for (int i = 0; i < 8; i++) {
            float h = sH[(tr * 8 + i) * 128 + k];
            acc2[i][0] = fmaf(h, wv.x, acc2[i][0]);
            acc2[i][1] = fmaf(h, wv.y, acc2[i][1]);
            acc2[i][2] = fmaf(h, wv.z, acc2[i][2]);
            acc2[i][3] = fmaf(h, wv.w, acc2[i][3]);
        }
    }

    // relu -> global
    #pragma unroll
    for (int i = 0; i < 8; i++) {
        float4 v;
        v.x = fmaxf(acc2[i][0], 0.f);
        v.y = fmaxf(acc2[i][1], 0.f);
        v.z = fmaxf(acc2[i][2], 0.f);
        v.w = fmaxf(acc2[i][3], 0.f);
        int g = g0 + tr * 8 + i;
        *(float4*)(out + (size_t)g * F2 + nn) = v;
    }
}

// ---------------------------------------------------------------------------
extern "C" void kernel_launch(void* const* d_in, const int* in_sizes, int n_in,
                              void* d_out, int out_size) {
    const float* in0 = (const float*)d_in[0];   // inputs0 (B, N1, 131)
    const float* in1 = (const float*)d_in[1];   // inputs1 (B, N2, 67)
    const float* W1  = (const float*)d_in[2];   // (192, 128)
    const float* b1  = (const float*)d_in[3];   // (128,)
    const float* W2  = (const float*)d_in[4];   // (128, 128)
    const float* b2  = (const float*)d_in[5];   // (128,)
    float* out = (float*)d_out;

    const int x_elems = BATCH * N2 * F2;                 // 8,388,608
    int write_xyz = (out_size >= x_elems + BATCH * N2 * 3) ? 1 : 0;

    const int mlp_smem = 37120 * (int)sizeof(float);     // 148,480 B
    cudaFuncSetAttribute(mlp_kernel, cudaFuncAttributeMaxDynamicSharedMemorySize, mlp_smem);

    pw_kernel<<<(BATCH * N1) / 8, 128>>>(in0, W1);
    knn_kernel<<<dim3(N2 / 256, BATCH), 256>>>(in0, in1, out + x_elems, write_xyz);
    mlp_kernel<<<(BATCH * N2) / 64, 256, mlp_smem>>>(in1, W1, b1, W2, b2, out);
}

// round 7
// speedup vs baseline: 1.0099x; 1.0099x over previous
#include <cuda_runtime.h>
#include <math_constants.h>

#define BATCH 2
#define N1 4096
#define N2 32768
#define C1 128
#define C2 64
#define F1 128
#define F2 128
#define IN0S 131   // 3 + C1
#define IN1S 67    // 3 + C2
#define KEPS 1e-7f

#define AST 68     // sA row stride (mod 32 = 4 -> conflict-free, mult of 4)
#define HST 136    // sH row stride (mod 32 = 8 -> conflict-free, mult of 4)

// Scratch (static device globals: allocation-free)
__device__ float g_PW[BATCH * N1 * F1];   // points1 @ W1[0:128,:]  (4 MB)
__device__ int   g_idx[BATCH * N2 * 3];
__device__ float g_w[BATCH * N2 * 3];

// ---------------------------------------------------------------------------
// K0: PW[b,j,f] = sum_c points1[b,j,c] * W1[c,f]   (rows 0..127 of W1)
// ---------------------------------------------------------------------------
__global__ void pw_kernel(const float* __restrict__ in0, const float* __restrict__ W1) {
    __shared__ float srow[8][128];
    int tid = threadIdx.x;
    long rowbase = (long)blockIdx.x * 8;
    #pragma unroll
    for (int r = 0; r < 8; r++)
        srow[r][tid] = in0[(rowbase + r) * IN0S + 3 + tid];
    __syncthreads();
    float acc[8];
    #pragma unroll
    for (int r = 0; r < 8; r++) acc[r] = 0.f;
    #pragma unroll 4
    for (int k = 0; k < 128; k++) {
        float w = __ldg(&W1[k * F1 + tid]);
        #pragma unroll
        for (int r = 0; r < 8; r++) acc[r] = fmaf(srow[r][k], w, acc[r]);
    }
    #pragma unroll
    for (int r = 0; r < 8; r++)
        g_PW[(rowbase + r) * F1 + tid] = acc[r];
}

// ---------------------------------------------------------------------------
// K1: brute-force 3-NN per query.
// Search in shifted space (|p|^2 - 2 p.q): 3 FFMA + 1 cmp per candidate.
// Exact (p-q)^2 recomputed for the 3 winners -> accurate weights.
// ---------------------------------------------------------------------------
__global__ void knn_kernel(const float* __restrict__ in0, const float* __restrict__ in1,
                           float* __restrict__ out_xyz, int write_xyz) {
    __shared__ float4 tile[1024];
    int b = blockIdx.y;
    int n = blockIdx.x * 256 + threadIdx.x;
    int g = b * N2 + n;
    const float* q = in1 + (size_t)g * IN1S;
    float qx = q[0], qy = q[1], qz = q[2];
    float nqx = -2.f * qx, nqy = -2.f * qy, nqz = -2.f * qz;
    float e0 = CUDART_INF_F, e1 = CUDART_INF_F, e2 = CUDART_INF_F;
    int i0 = 0, i1 = 0, i2 = 0;

    for (int t = 0; t < N1 / 1024; t++) {
        for (int s = threadIdx.x; s < 1024; s += 256) {
            const float* p = in0 + (size_t)(b * N1 + t * 1024 + s) * IN0S;
            float px = p[0], py = p[1], pz = p[2];
            tile[s] = make_float4(px, py, pz, fmaf(px, px, fmaf(py, py, pz * pz)));
        }
        __syncthreads();
        #pragma unroll 4
        for (int s = 0; s < 1024; s++) {
            float4 p = tile[s];
            float d = fmaf(p.x, nqx, p.w);
            d = fmaf(p.y, nqy, d);
            d = fmaf(p.z, nqz, d);
            if (d < e2) {
                int j = t * 1024 + s;
                if (d < e1) {
                    e2 = e1; i2 = i1;
                    if (d < e0) { e1 = e0; i1 = i0; e0 = d; i0 = j; }
                    else        { e1 = d;  i1 = j; }
                } else { e2 = d; i2 = j; }
            }
        }
        __syncthreads();
    }

    // Exact distance recompute for winners (avoids |p|^2-2pq+|q|^2 cancellation)
    const float* P = in0 + (size_t)(b * N1) * IN0S;
    float d0, d1, d2;
    {
        const float* p = P + (size_t)i0 * IN0S;
        float dx = p[0] - qx, dy = p[1] - qy, dz = p[2] - qz;
        d0 = fmaxf(fmaf(dx, dx, fmaf(dy, dy, dz * dz)), KEPS);
        p = P + (size_t)i1 * IN0S;
        dx = p[0] - qx; dy = p[1] - qy; dz = p[2] - qz;
        d1 = fmaxf(fmaf(dx, dx, fmaf(dy, dy, dz * dz)), KEPS);
        p = P + (size_t)i2 * IN0S;
        dx = p[0] - qx; dy = p[1] - qy; dz = p[2] - qz;
        d2 = fmaxf(fmaf(dx, dx, fmaf(dy, dy, dz * dz)), KEPS);
    }
    float w0 = 1.f / d0, w1 = 1.f / d1, w2 = 1.f / d2;
    float inv = 1.f / (w0 + w1 + w2);
    g_idx[g * 3 + 0] = i0; g_idx[g * 3 + 1] = i1; g_idx[g * 3 + 2] = i2;
    g_w[g * 3 + 0] = w0 * inv; g_w[g * 3 + 1] = w1 * inv; g_w[g * 3 + 2] = w2 * inv;
    if (write_xyz) {
        out_xyz[(size_t)g * 3 + 0] = qx;
        out_xyz[(size_t)g * 3 + 1] = qy;
        out_xyz[(size_t)g * 3 + 2] = qz;
    }
}

// ---------------------------------------------------------------------------
// K2: fused MLP v2. 128-query tile, 256 threads, 8x8 register sub-tiles.
// Thread (ty,tx): ty=tid>>4, tx=tid&15; rows ty+16*i, cols tx*8..tx*8+7.
// Each output cell owned by exactly one thread (init-read/relu-write race-free).
// smem: W2 64K + W1b 32K + A(128x68) 34.8K + H(128x136) 69.6K + biases ~ 204KB
// ---------------------------------------------------------------------------
__global__ void mlp_kernel(const float* __restrict__ in1, const float* __restrict__ W1,
                           const float* __restrict__ b1, const float* __restrict__ W2,
                           const float* __restrict__ b2, float* __restrict__ out) {
    extern __shared__ float sm[];
    float* sW2  = sm;                 // 16384
    float* sW1b = sW2 + 16384;        //  8192
    float* sA   = sW1b + 8192;        //  128*AST = 8704
    float* sH   = sA + 128 * AST;     //  128*HST = 17408
    float* sB1  = sH + 128 * HST;     //   128
    float* sB2  = sB1 + 128;          //   128

    int tid = threadIdx.x;
    int g0 = blockIdx.x * 128;         // first query of tile
    int bb = g0 / N2;                  // batch (tiles never straddle batches)

    for (int i = tid; i < 16384; i += 256) sW2[i] = W2[i];
    for (int i = tid; i < 8192;  i += 256) sW1b[i] = W1[C1 * F1 + i];
    if (tid < 128) { sB1[tid] = b1[tid]; sB2[tid] = b2[tid]; }
    for (int i = tid; i < 128 * 64; i += 256) {
        int m = i >> 6, c = i & 63;
        sA[m * AST + c] = in1[(size_t)(g0 + m) * IN1S + 3 + c];
    }
    __syncthreads();

    // Gather interpolation in projected space -> sH (2 threads per query row)
    {
        int m  = tid >> 1;             // query row 0..127
        int fo = (tid & 1) * 64;       // feature half
        int g  = g0 + m;
        int j0 = g_idx[g * 3 + 0], j1 = g_idx[g * 3 + 1], j2 = g_idx[g * 3 + 2];
        float w0 = g_w[g * 3 + 0], w1 = g_w[g * 3 + 1], w2 = g_w[g * 3 + 2];
        const float* Pg = g_PW + (size_t)bb * N1 * F1;
        const float* p0 = Pg + (size_t)j0 * F1;
        const float* p1 = Pg + (size_t)j1 * F1;
        const float* p2 = Pg + (size_t)j2 * F1;
        #pragma unroll
        for (int u = 0; u < 64; u += 4) {
            int f = fo + u;
            float4 a  = *(const float4*)(p0 + f);
            float4 c4 = *(const float4*)(p1 + f);
            float4 e4 = *(const float4*)(p2 + f);
            float4 bv = *(const float4*)(sB1 + f);
            float4 r;
            r.x = bv.x + w0 * a.x + w1 * c4.x + w2 * e4.x;
            r.y = bv.y + w0 * a.y + w1 * c4.y + w2 * e4.y;
            r.z = bv.z + w0 * a.z + w1 * c4.z + w2 * e4.z;
            r.w = bv.w + w0 * a.w + w1 * c4.w + w2 * e4.w;
            *(float4*)(sH + m * HST + f) = r;
        }
    }
    __syncthreads();

    int ty = tid >> 4, tx = tid & 15;
    int nn = tx * 8;

    // init accumulators from gathered interp (+b1) in sH
    float acc[8][8];
    #pragma unroll
    for (int i = 0; i < 8; i++) {
        int r = ty + 16 * i;
        float4 v0 = *(const float4*)(sH + r * HST + nn);
        float4 v1 = *(const float4*)(sH + r * HST + nn + 4);
        acc[i][0] = v0.x; acc[i][1] = v0.y; acc[i][2] = v0.z; acc[i][3] = v0.w;
        acc[i][4] = v1.x; acc[i][5] = v1.y; acc[i][6] = v1.z; acc[i][7] = v1.w;
    }

    // GEMM1: A(128x64) @ W1b(64x128)
    #pragma unroll 4
    for (int k = 0; k < 64; k++) {
        float4 w0 = *(const float4*)(sW1b + k * 128 + nn);
        float4 w1 = *(const float4*)(sW1b + k * 128 + nn + 4);
        #pragma unroll
        for (int i = 0; i < 8; i++) {
            float a = sA[(ty + 16 * i) * AST + k];
            acc[i][0] = fmaf(a, w0.x, acc[i][0]);
            acc[i][1] = fmaf(a, w0.y, acc[i][1]);
            acc[i][2] = fmaf(a, w0.z, acc[i][2]);
            acc[i][3] = fmaf(a, w0.w, acc[i][3]);
            acc[i][4] = fmaf(a, w1.x, acc[i][4]);
            acc[i][5] = fmaf(a, w1.y, acc[i][5]);
            acc[i][6] = fmaf(a, w1.z, acc[i][6]);
            acc[i][7] = fmaf(a, w1.w, acc[i][7]);
        }
    }

    // relu -> sH (same cells this thread read: no cross-thread race)
    #pragma unroll
    for (int i = 0; i < 8; i++) {
        int r = ty + 16 * i;
        float4 v0, v1;
        v0.x = fmaxf(acc[i][0], 0.f); v0.y = fmaxf(acc[i][1], 0.f);
        v0.z = fmaxf(acc[i][2], 0.f); v0.w = fmaxf(acc[i][3], 0.f);
        v1.x = fmaxf(acc[i][4], 0.f); v1.y = fmaxf(acc[i][5], 0.f);
        v1.z = fmaxf(acc[i][6], 0.f); v1.w = fmaxf(acc[i][7], 0.f);
        *(float4*)(sH + r * HST + nn) = v0;
        *(float4*)(sH + r * HST + nn + 4) = v1;
    }
    __syncthreads();

    // GEMM2: H(128x128) @ W2(128x128)
    float4 b2a = *(const float4*)(sB2 + nn);
    float4 b2b = *(const float4*)(sB2 + nn + 4);
    float acc2[8][8];
    #pragma unroll
    for (int i = 0; i < 8; i++) {
        acc2[i][0] = b2a.x; acc2[i][1] = b2a.y; acc2[i][2] = b2a.z; acc2[i][3] = b2a.w;
        acc2[i][4] = b2b.x; acc2[i][5] = b2b.y; acc2[i][6] = b2b.z; acc2[i][7] = b2b.w;
    }
    #pragma unroll 2
    for (int k = 0; k < 128; k++) {
        float4 w0 = *(const float4*)(sW2 + k * 128 + nn);
        float4 w1 = *(const float4*)(sW2 + k * 128 + nn + 4);
        #pragma unroll
        for (int i = 0; i < 8; i++) {
            float h = sH[(ty + 16 * i) * HST + k];
            acc2[i][0] = fmaf(h, w0.x, acc2[i][0]);
            acc2[i][1] = fmaf(h, w0.y, acc2[i][1]);
            acc2[i][2] = fmaf(h, w0.z, acc2[i][2]);
            acc2[i][3] = fmaf(h, w0.w, acc2[i][3]);
            acc2[i][4] = fmaf(h, w1.x, acc2[i][4]);
            acc2[i][5] = fmaf(h, w1.y, acc2[i][5]);
            acc2[i][6] = fmaf(h, w1.z, acc2[i][6]);
            acc2[i][7] = fmaf(h, w1.w, acc2[i][7]);
        }
    }

    // relu -> global
    #pragma unroll
    for (int i = 0; i < 8; i++) {
        int g = g0 + ty + 16 * i;
        float4 v0, v1;
        v0.x = fmaxf(acc2[i][0], 0.f); v0.y = fmaxf(acc2[i][1], 0.f);
        v0.z = fmaxf(acc2[i][2], 0.f); v0.w = fmaxf(acc2[i][3], 0.f);
        v1.x = fmaxf(acc2[i][4], 0.f); v1.y = fmaxf(acc2[i][5], 0.f);
        v1.z = fmaxf(acc2[i][6], 0.f); v1.w = fmaxf(acc2[i][7], 0.f);
        *(float4*)(out + (size_t)g * F2 + nn) = v0;
        *(float4*)(out + (size_t)g * F2 + nn + 4) = v1;
    }
}

// ---------------------------------------------------------------------------
extern "C" void kernel_launch(void* const* d_in, const int* in_sizes, int n_in,
                              void* d_out, int out_size) {
    const float* in0 = (const float*)d_in[0];   // inputs0 (B, N1, 131)
    const float* in1 = (const float*)d_in[1];   // inputs1 (B, N2, 67)
    const float* W1  = (const float*)d_in[2];   // (192, 128)
    const float* b1  = (const float*)d_in[3];   // (128,)
    const float* W2  = (const float*)d_in[4];   // (128, 128)
    const float* b2  = (const float*)d_in[5];   // (128,)
    float* out = (float*)d_out;

    const int x_elems = BATCH * N2 * F2;                 // 8,388,608
    int write_xyz = (out_size >= x_elems + BATCH * N2 * 3) ? 1 : 0;

    const int mlp_smem = (16384 + 8192 + 128 * AST + 128 * HST + 256) * (int)sizeof(float);
    cudaFuncSetAttribute(mlp_kernel, cudaFuncAttributeMaxDynamicSharedMemorySize, mlp_smem);

    knn_kernel<<<dim3(N2 / 256, BATCH), 256>>>(in0, in1, out + x_elems, write_xyz);
    pw_kernel<<<(BATCH * N1) / 8, 128>>>(in0, W1);
    mlp_kernel<<<(BATCH * N2) / 128, 256, mlp_smem>>>(in1, W1, b1, W2, b2, out);
}

// round 9
// speedup vs baseline: 1.0460x; 1.0357x over previous
#include <cuda_runtime.h>
#include <math_constants.h>

#define BATCH 2
#define N1 4096
#define N2 32768
#define C1 128
#define C2 64
#define F1 128
#define F2 128
#define IN0S 131   // 3 + C1
#define IN1S 67    // 3 + C2
#define KEPS 1e-7f

#define AST 68     // sA row stride (mod 32 = 4 -> conflict-free, mult of 4)
#define HST 136    // sH row stride (mod 32 = 8 -> conflict-free, mult of 4)

#define NSLICE 4               // candidate-dim split
#define CPT (N1 / NSLICE)      // 1024 candidates per slice

// Scratch (static device globals: allocation-free)
__device__ float g_PW[BATCH * N1 * F1];          // points1 @ W1[0:128,:]
__device__ int   g_idx[BATCH * N2 * 3];
__device__ float g_w[BATCH * N2 * 3];
__device__ float g_pd[BATCH * N2 * NSLICE * 3];  // partial top-3 dists (shifted)
__device__ int   g_pi[BATCH * N2 * NSLICE * 3];  // partial top-3 indices

// ---------------------------------------------------------------------------
// K0: PW[b,j,f] = sum_c points1[b,j,c] * W1[c,f]   (rows 0..127 of W1)
// ---------------------------------------------------------------------------
__global__ void pw_kernel(const float* __restrict__ in0, const float* __restrict__ W1) {
    __shared__ float srow[8][128];
    int tid = threadIdx.x;
    long rowbase = (long)blockIdx.x * 8;
    #pragma unroll
    for (int r = 0; r < 8; r++)
        srow[r][tid] = in0[(rowbase + r) * IN0S + 3 + tid];
    __syncthreads();
    float acc[8];
    #pragma unroll
    for (int r = 0; r < 8; r++) acc[r] = 0.f;
    #pragma unroll 4
    for (int k = 0; k < 128; k++) {
        float w = __ldg(&W1[k * F1 + tid]);
        #pragma unroll
        for (int r = 0; r < 8; r++) acc[r] = fmaf(srow[r][k], w, acc[r]);
    }
    #pragma unroll
    for (int r = 0; r < 8; r++)
        g_PW[(rowbase + r) * F1 + tid] = acc[r];
}

// ---------------------------------------------------------------------------
// K1a: partial 3-NN. Each block: 512 queries (2 per thread) x 1024 candidates.
// Shifted-space distance |p|^2 - 2 p.q : 3 FFMA + 1 cmp per cand per query.
// grid = (N2/512, NSLICE, BATCH)
// ---------------------------------------------------------------------------
__global__ void knn_part_kernel(const float* __restrict__ in0,
                                const float* __restrict__ in1) {
    __shared__ float4 tile[CPT];
    int tid = threadIdx.x;
    int b  = blockIdx.z;
    int sl = blockIdx.y;
    int cs = sl * CPT;                     // candidate slice start
    int qA = blockIdx.x * 512 + tid;       // query A
    int qB = qA + 256;                     // query B
    int gA = b * N2 + qA;
    int gB = b * N2 + qB;

    const float* q = in1 + (size_t)gA * IN1S;
    float axq = q[0], ayq = q[1], azq = q[2];
    q = in1 + (size_t)gB * IN1S;
    float bxq = q[0], byq = q[1], bzq = q[2];
    float nAx = -2.f * axq, nAy = -2.f * ayq, nAz = -2.f * azq;
    float nBx = -2.f * bxq, nBy = -2.f * byq, nBz = -2.f * bzq;

    // fill tile
    for (int s = tid; s < CPT; s += 256) {
        const float* p = in0 + (size_t)(b * N1 + cs + s) * IN0S;
        float px = p[0], py = p[1], pz = p[2];
        tile[s] = make_float4(px, py, pz, fmaf(px, px, fmaf(py, py, pz * pz)));
    }
    __syncthreads();

    float eA0 = CUDART_INF_F, eA1 = CUDART_INF_F, eA2 = CUDART_INF_F;
    float eB0 = CUDART_INF_F, eB1 = CUDART_INF_F, eB2 = CUDART_INF_F;
    int iA0 = 0, iA1 = 0, iA2 = 0, iB0 = 0, iB1 = 0, iB2 = 0;

    #pragma unroll 8
    for (int s = 0; s < CPT; s++) {
        float4 p = tile[s];
        float dA = fmaf(p.x, nAx, p.w);
        dA = fmaf(p.y, nAy, dA);
        dA = fmaf(p.z, nAz, dA);
        float dB = fmaf(p.x, nBx, p.w);
        dB = fmaf(p.y, nBy, dB);
        dB = fmaf(p.z, nBz, dB);
        if (dA < eA2) {
            int j = cs + s;
            if (dA < eA1) {
                eA2 = eA1; iA2 = iA1;
                if (dA < eA0) { eA1 = eA0; iA1 = iA0; eA0 = dA; iA0 = j; }
                else          { eA1 = dA;  iA1 = j; }
            } else { eA2 = dA; iA2 = j; }
        }
        if (dB < eB2) {
            int j = cs + s;
            if (dB < eB1) {
                eB2 = eB1; iB2 = iB1;
                if (dB < eB0) { eB1 = eB0; iB1 = iB0; eB0 = dB; iB0 = j; }
                else          { eB1 = dB;  iB1 = j; }
            } else { eB2 = dB; iB2 = j; }
        }
    }

    size_t oA = ((size_t)gA * NSLICE + sl) * 3;
    size_t oB = ((size_t)gB * NSLICE + sl) * 3;
    g_pd[oA + 0] = eA0; g_pd[oA + 1] = eA1; g_pd[oA + 2] = eA2;
    g_pi[oA + 0] = iA0; g_pi[oA + 1] = iA1; g_pi[oA + 2] = iA2;
    g_pd[oB + 0] = eB0; g_pd[oB + 1] = eB1; g_pd[oB + 2] = eB2;
    g_pi[oB + 0] = iB0; g_pi[oB + 1] = iB1; g_pi[oB + 2] = iB2;
}

// ---------------------------------------------------------------------------
// K1b: merge NSLICE partial top-3s per query (slice order + strict < keeps
// lowest-index tie-break identical to a sequential scan), exact-distance
// recompute for the winners, weights + xyz output.
// ---------------------------------------------------------------------------
__global__ void knn_merge_kernel(const float* __restrict__ in0,
                                 const float* __restrict__ in1,
                                 float* __restrict__ out_xyz, int write_xyz) {
    int g = blockIdx.x * 256 + threadIdx.x;   // global query in [0, BATCH*N2)
    int b = g / N2;

    float e0 = CUDART_INF_F, e1 = CUDART_INF_F, e2 = CUDART_INF_F;
    int i0 = 0, i1 = 0, i2 = 0;
    size_t base = (size_t)g * NSLICE * 3;
    #pragma unroll
    for (int t = 0; t < NSLICE * 3; t++) {
        float d = g_pd[base + t];
        int   j = g_pi[base + t];
        if (d < e2) {
            if (d < e1) {
                e2 = e1; i2 = i1;
                if (d < e0) { e1 = e0; i1 = i0; e0 = d; i0 = j; }
                else        { e1 = d;  i1 = j; }
            } else { e2 = d; i2 = j; }
        }
    }

    const float* q = in1 + (size_t)g * IN1S;
    float qx = q[0], qy = q[1], qz = q[2];

    const float* P = in0 + (size_t)(b * N1) * IN0S;
    const float* p = P + (size_t)i0 * IN0S;
    float dx = p[0] - qx, dy = p[1] - qy, dz = p[2] - qz;
    float d0 = fmaxf(fmaf(dx, dx, fmaf(dy, dy, dz * dz)), KEPS);
    p = P + (size_t)i1 * IN0S;
    dx = p[0] - qx; dy = p[1] - qy; dz = p[2] - qz;
    float d1 = fmaxf(fmaf(dx, dx, fmaf(dy, dy, dz * dz)), KEPS);
    p = P + (size_t)i2 * IN0S;
    dx = p[0] - qx; dy = p[1] - qy; dz = p[2] - qz;
    float d2 = fmaxf(fmaf(dx, dx, fmaf(dy, dy, dz * dz)), KEPS);

    float w0 = 1.f / d0, w1 = 1.f / d1, w2 = 1.f / d2;
    float inv = 1.f / (w0 + w1 + w2);
    g_idx[g * 3 + 0] = i0; g_idx[g * 3 + 1] = i1; g_idx[g * 3 + 2] = i2;
    g_w[g * 3 + 0] = w0 * inv; g_w[g * 3 + 1] = w1 * inv; g_w[g * 3 + 2] = w2 * inv;
    if (write_xyz) {
        out_xyz[(size_t)g * 3 + 0] = qx;
        out_xyz[(size_t)g * 3 + 1] = qy;
        out_xyz[(size_t)g * 3 + 2] = qz;
    }
}

// ---------------------------------------------------------------------------
// K2: fused MLP. 128-query tile, 256 threads, 8x8 register sub-tiles.
// ---------------------------------------------------------------------------
__global__ void mlp_kernel(const float* __restrict__ in1, const float* __restrict__ W1,
                           const float* __restrict__ b1, const float* __restrict__ W2,
                           const float* __restrict__ b2, float* __restrict__ out) {
    extern __shared__ float sm[];
    float* sW2  = sm;                 // 16384
    float* sW1b = sW2 + 16384;        //  8192
    float* sA   = sW1b + 8192;        //  128*AST
    float* sH   = sA + 128 * AST;     //  128*HST
    float* sB1  = sH + 128 * HST;     //   128
    float* sB2  = sB1 + 128;          //   128

    int tid = threadIdx.x;
    int g0 = blockIdx.x * 128;
    int bb = g0 / N2;

    for (int i = tid; i < 16384; i += 256) sW2[i] = W2[i];
    for (int i = tid; i < 8192;  i += 256) sW1b[i] = W1[C1 * F1 + i];
    if (tid < 128) { sB1[tid] = b1[tid]; sB2[tid] = b2[tid]; }
    for (int i = tid; i < 128 * 64; i += 256) {
        int m = i >> 6, c = i & 63;
        sA[m * AST + c] = in1[(size_t)(g0 + m) * IN1S + 3 + c];
    }
    __syncthreads();

    // Gather interpolation in projected space -> sH (2 threads per query row)
    {
        int m  = tid >> 1;
        int fo = (tid & 1) * 64;
        int g  = g0 + m;
        int j0 = g_idx[g * 3 + 0], j1 = g_idx[g * 3 + 1], j2 = g_idx[g * 3 + 2];
        float w0 = g_w[g * 3 + 0], w1 = g_w[g * 3 + 1], w2 = g_w[g * 3 + 2];
        const float* Pg = g_PW + (size_t)bb * N1 * F1;
        const float* p0 = Pg + (size_t)j0 * F1;
        const float* p1 = Pg + (size_t)j1 * F1;
        const float* p2 = Pg + (size_t)j2 * F1;
        #pragma unroll
        for (int u = 0; u < 64; u += 4) {
            int f = fo + u;
            float4 a  = *(const float4*)(p0 + f);
            float4 c4 = *(const float4*)(p1 + f);
            float4 e4 = *(const float4*)(p2 + f);
            float4 bv = *(const float4*)(sB1 + f);
            float4 r;
            r.x = bv.x + w0 * a.x + w1 * c4.x + w2 * e4.x;
            r.y = bv.y + w0 * a.y + w1 * c4.y + w2 * e4.y;
            r.z = bv.z + w0 * a.z + w1 * c4.z + w2 * e4.z;
            r.w = bv.w + w0 * a.w + w1 * c4.w + w2 * e4.w;
            *(float4*)(sH + m * HST + f) = r;
        }
    }
    __syncthreads();

    int ty = tid >> 4, tx = tid & 15;
    int nn = tx * 8;

    float acc[8][8];
    #pragma unroll
    for (int i = 0; i < 8; i++) {
        int r = ty + 16 * i;
        float4 v0 = *(const float4*)(sH + r * HST + nn);
        float4 v1 = *(const float4*)(sH + r * HST + nn + 4);
        acc[i][0] = v0.x; acc[i][1] = v0.y; acc[i][2] = v0.z; acc[i][3] = v0.w;
        acc[i][4] = v1.x; acc[i][5] = v1.y; acc[i][6] = v1.z; acc[i][7] = v1.w;
    }

    #pragma unroll 4
    for (int k = 0; k < 64; k++) {
        float4 w0 = *(const float4*)(sW1b + k * 128 + nn);
        float4 w1 = *(const float4*)(sW1b + k * 128 + nn + 4);
        #pragma unroll
        for (int i = 0; i < 8; i++) {
            float a = sA[(ty + 16 * i) * AST + k];
            acc[i][0] = fmaf(a, w0.x, acc[i][0]);
            acc[i][1] = fmaf(a, w0.y, acc[i][1]);
            acc[i][2] = fmaf(a, w0.z, acc[i][2]);
            acc[i][3] = fmaf(a, w0.w, acc[i][3]);
            acc[i][4] = fmaf(a, w1.x, acc[i][4]);
            acc[i][5] = fmaf(a, w1.y, acc[i][5]);
            acc[i][6] = fmaf(a, w1.z, acc[i][6]);
            acc[i][7] = fmaf(a, w1.w, acc[i][7]);
        }
    }

    #pragma unroll
    for (int i = 0; i < 8; i++) {
        int r = ty + 16 * i;
        float4 v0, v1;
        v0.x = fmaxf(acc[i][0], 0.f); v0.y = fmaxf(acc[i][1], 0.f);
        v0.z = fmaxf(acc[i][2], 0.f); v0.w = fmaxf(acc[i][3], 0.f);
        v1.x = fmaxf(acc[i][4], 0.f); v1.y = fmaxf(acc[i][5], 0.f);
        v1.z = fmaxf(acc[i][6], 0.f); v1.w = fmaxf(acc[i][7], 0.f);
        *(float4*)(sH + r * HST + nn) = v0;
        *(float4*)(sH + r * HST + nn + 4) = v1;
    }
    __syncthreads();

    float4 b2a = *(const float4*)(sB2 + nn);
    float4 b2b = *(const float4*)(sB2 + nn + 4);
    float acc2[8][8];
    #pragma unroll
    for (int i = 0; i < 8; i++) {
        acc2[i][0] = b2a.x; acc2[i][1] = b2a.y; acc2[i][2] = b2a.z; acc2[i][3] = b2a.w;
        acc2[i][4] = b2b.x; acc2[i][5] = b2b.y; acc2[i][6] = b2b.z; acc2[i][7] = b2b.w;
    }
    #pragma unroll 2
    for (int k = 0; k < 128; k++) {
        float4 w0 = *(const float4*)(sW2 + k * 128 + nn);
        float4 w1 = *(const float4*)(sW2 + k * 128 + nn + 4);
        #pragma unroll
        for (int i = 0; i < 8; i++) {
            float h = sH[(ty + 16 * i) * HST + k];
            acc2[i][0] = fmaf(h, w0.x, acc2[i][0]);
            acc2[i][1] = fmaf(h, w0.y, acc2[i][1]);
            acc2[i][2] = fmaf(h, w0.z, acc2[i][2]);
            acc2[i][3] = fmaf(h, w0.w, acc2[i][3]);
            acc2[i][4] = fmaf(h, w1.x, acc2[i][4]);
            acc2[i][5] = fmaf(h, w1.y, acc2[i][5]);
            acc2[i][6] = fmaf(h, w1.z, acc2[i][6]);
            acc2[i][7] = fmaf(h, w1.w, acc2[i][7]);
        }
    }

    #pragma unroll
    for (int i = 0; i < 8; i++) {
        int g = g0 + ty + 16 * i;
        float4 v0, v1;
        v0.x = fmaxf(acc2[i][0], 0.f); v0.y = fmaxf(acc2[i][1], 0.f);
        v0.z = fmaxf(acc2[i][2], 0.f); v0.w = fmaxf(acc2[i][3], 0.f);
        v1.x = fmaxf(acc2[i][4], 0.f); v1.y = fmaxf(acc2[i][5], 0.f);
        v1.z = fmaxf(acc2[i][6], 0.f); v1.w = fmaxf(acc2[i][7], 0.f);
        *(float4*)(out + (size_t)g * F2 + nn) = v0;
        *(float4*)(out + (size_t)g * F2 + nn + 4) = v1;
    }
}

// ---------------------------------------------------------------------------
extern "C" void kernel_launch(void* const* d_in, const int* in_sizes, int n_in,
                              void* d_out, int out_size) {
    const float* in0 = (const float*)d_in[0];   // inputs0 (B, N1, 131)
    const float* in1 = (const float*)d_in[1];   // inputs1 (B, N2, 67)
    const float* W1  = (const float*)d_in[2];   // (192, 128)
    const float* b1  = (const float*)d_in[3];   // (128,)
    const float* W2  = (const float*)d_in[4];   // (128, 128)
    const float* b2  = (const float*)d_in[5];   // (128,)
    float* out = (float*)d_out;

    const int x_elems = BATCH * N2 * F2;                 // 8,388,608
    int write_xyz = (out_size >= x_elems + BATCH * N2 * 3) ? 1 : 0;

    const int mlp_smem = (16384 + 8192 + 128 * AST + 128 * HST + 256) * (int)sizeof(float);
    cudaFuncSetAttribute(mlp_kernel, cudaFuncAttributeMaxDynamicSharedMemorySize, mlp_smem);

    knn_part_kernel<<<dim3(N2 / 512, NSLICE, BATCH), 256>>>(in0, in1);
    pw_kernel<<<(BATCH * N1) / 8, 128>>>(in0, W1);
    knn_merge_kernel<<<(BATCH * N2) / 256, 256>>>(in0, in1, out + x_elems, write_xyz);
    mlp_kernel<<<(BATCH * N2) / 128, 256, mlp_smem>>>(in1, W1, b1, W2, b2, out);
}